// round 7
// baseline (speedup 1.0000x reference)
#include <cuda_runtime.h>

#define NB    64
#define NV    4096
#define NFEAT 16
#define NA    8
#define NP    16
#define NOUT  16
#define S1    16                 // blocks per batch
#define CH    256                // vertices per block
#define GRID1 (NB * S1)          // 1024

// Per-(b,split) partials; slot owned exclusively -> no zeroing kernel.
__device__ float    g_part[GRID1 * 128];
// Per-batch M[a][n] from the fan-in block.
__device__ float    g_M[NB * 128];
// Monotonic per-batch counters (never reset; epoch = count/S1, replay-safe).
__device__ unsigned g_cnt[NB];
__device__ unsigned g_flag[NB];

__global__ __launch_bounds__(256, 3) void garnet(
    const float* __restrict__ data, const int* __restrict__ num_vertex,
    const float* __restrict__ W_flr, const float* __restrict__ b_flr,
    const float* __restrict__ W_s,   const float* __restrict__ b_s,
    const float* __restrict__ W_out, const float* __restrict__ b_out,
    float* __restrict__ out)
{
    __shared__ float4 sWf4[NFEAT][4];
    __shared__ float4 sWs4[NFEAT][2];
    __shared__ float  sbf[NP];
    __shared__ float  sbs[NA];
    __shared__ float  sbo[NOUT];
    __shared__ float4 sStage[CH * 6];   // [0..3]=feat, [4..5]=ew; reused as sRed
    __shared__ float  sFan[128];
    __shared__ __align__(16) float sM[128];
    __shared__ unsigned sEpoch, sLast;

    const int t     = threadIdx.x;
    const int b     = blockIdx.x / S1;
    const int split = blockIdx.x % S1;
    const int nv    = num_vertex[b];
    const int vbase = split * CH;
    const int v     = vbase + t;
    const bool work = (vbase < nv);      // block-uniform
    const float4 z  = make_float4(0.f, 0.f, 0.f, 0.f);

    float4 e0 = z, e1 = z;               // this thread's ew, kept in regs

    if (work) {
        if (t < 64) {
            sWf4[t >> 2][t & 3] = ((const float4*)W_flr)[t];
        } else if (t < 96) {
            const int u = t - 64;
            sWs4[u >> 1][u & 1] = ((const float4*)W_s)[u];
        } else if (t < 112) {
            sbf[t - 96] = b_flr[t - 96];
        } else if (t < 120) {
            sbs[t - 112] = b_s[t - 112];
        } else if (t < 136) {
            sbo[t - 120] = b_out[t - 120];
        }
        __syncthreads();

        if (v < nv) {
            const float4* dp = (const float4*)(data + ((size_t)(b * NV + v)) * NFEAT);
            const float4 x0 = dp[0], x1 = dp[1], x2 = dp[2], x3 = dp[3];
            float x[16];
            x[0]=x0.x;  x[1]=x0.y;  x[2]=x0.z;  x[3]=x0.w;
            x[4]=x1.x;  x[5]=x1.y;  x[6]=x1.z;  x[7]=x1.w;
            x[8]=x2.x;  x[9]=x2.y;  x[10]=x2.z; x[11]=x2.w;
            x[12]=x3.x; x[13]=x3.y; x[14]=x3.z; x[15]=x3.w;

            #pragma unroll
            for (int g = 0; g < 4; ++g) {
                float s0 = sbf[g*4+0], s1 = sbf[g*4+1];
                float s2 = sbf[g*4+2], s3 = sbf[g*4+3];
                #pragma unroll
                for (int f = 0; f < 16; ++f) {
                    const float4 w = sWf4[f][g];
                    s0 += x[f]*w.x; s1 += x[f]*w.y;
                    s2 += x[f]*w.z; s3 += x[f]*w.w;
                }
                sStage[t*6 + g] = make_float4(s0, s1, s2, s3);
            }
            {
                float s0 = sbs[0], s1 = sbs[1], s2 = sbs[2], s3 = sbs[3];
                float u0 = sbs[4], u1 = sbs[5], u2 = sbs[6], u3 = sbs[7];
                #pragma unroll
                for (int f = 0; f < 16; ++f) {
                    const float4 w0 = sWs4[f][0];
                    const float4 w1 = sWs4[f][1];
                    s0 += x[f]*w0.x; s1 += x[f]*w0.y;
                    s2 += x[f]*w0.z; s3 += x[f]*w0.w;
                    u0 += x[f]*w1.x; u1 += x[f]*w1.y;
                    u2 += x[f]*w1.z; u3 += x[f]*w1.w;
                }
                e0 = make_float4(__expf(-s0*s0), __expf(-s1*s1),
                                 __expf(-s2*s2), __expf(-s3*s3));
                e1 = make_float4(__expf(-u0*u0), __expf(-u1*u1),
                                 __expf(-u2*u2), __expf(-u3*u3));
                sStage[t*6 + 4] = e0;
                sStage[t*6 + 5] = e1;
            }
        } else {
            #pragma unroll
            for (int g = 0; g < 6; ++g) sStage[t*6 + g] = z;
        }
        __syncthreads();

        // 32 owners (aa=o>>2, pg=o&3) x 8 slices of 32 vertices
        const int owner = t & 31;
        const int aa    = owner >> 2;
        const int pg    = owner & 3;
        const int slice = t >> 5;
        const float* sS = (const float*)sStage;
        float4 acc = z;
        const int v0 = slice * 32;
        #pragma unroll 4
        for (int i = 0; i < 32; ++i) {
            const int vv = v0 + i;
            const float  w = sS[vv*24 + 16 + aa];
            const float4 f = sStage[vv*6 + pg];
            acc.x += w * f.x; acc.y += w * f.y;
            acc.z += w * f.z; acc.w += w * f.w;
        }
        __syncthreads();

        float4* sRed = sStage;               // ew already safe in regs
        sRed[slice * 32 + owner] = acc;
        __syncthreads();
        if (t < 32) {
            float4 s = sRed[t];
            #pragma unroll
            for (int sl = 1; sl < 8; ++sl) {
                const float4 r = sRed[sl * 32 + t];
                s.x += r.x; s.y += r.y; s.z += r.z; s.w += r.w;
            }
            ((float4*)g_part)[blockIdx.x * 32 + t] = s;
            __threadfence();                 // release this lane's partial
        }
    } else {
        if (t < 32) {
            ((float4*)g_part)[blockIdx.x * 32 + t] = z;
            __threadfence();
        }
    }
    __syncthreads();                         // all partial stores fenced before arrival

    // ---- per-batch arrival; last block does fan-in and publishes M ----
    if (t == 0) {
        const unsigned old = atomicAdd(&g_cnt[b], 1u);
        sEpoch = old / (unsigned)S1;
        sLast  = ((old & (S1 - 1)) == (S1 - 1)) ? 1u : 0u;
    }
    __syncthreads();

    if (sLast) {
        __threadfence();                     // acquire siblings' partials
        if (t < 32) {
            float4 s = z;
            #pragma unroll
            for (int sp = 0; sp < S1; ++sp) {
                const float4 r = ((const float4*)g_part)[(b * S1 + sp) * 32 + t];
                s.x += r.x; s.y += r.y; s.z += r.z; s.w += r.w;
            }
            const float inv = 1.0f / (float)NV;
            s.x *= inv; s.y *= inv; s.z *= inv; s.w *= inv;
            ((float4*)sFan)[t] = s;          // agg[a*16+p]
        }
        __syncthreads();
        if (t < 128) {
            const int a = t >> 4, n = t & 15;
            float m = 0.f;
            #pragma unroll
            for (int p = 0; p < NP; ++p)
                m += sFan[a*NP + p] * W_out[(a*NP + p)*NOUT + n];
            g_M[b * 128 + t] = m;
            sM[t] = m;                       // local copy, skip re-read
            __threadfence();                 // release M
        }
        __syncthreads();
        if (t == 0) atomicAdd(&g_flag[b], 1u);
        __syncthreads();
    } else if (work) {
        if (t == 0) {
            const unsigned target = sEpoch + 1u;
            while (*(volatile unsigned*)&g_flag[b] < target) { __nanosleep(32); }
        }
        __syncthreads();
        __threadfence();                     // acquire M
        if (t < 32) ((float4*)sM)[t] = ((const float4*)g_M)[b * 32 + t];
        __syncthreads();
    }
    // blocks with !work && !sLast skip waiting entirely (they output zeros)

    // ---- output: this thread's vertex, ew from registers ----
    float4* op = (float4*)(out + ((size_t)(b * NV + v)) * NOUT);
    if (work && v < nv) {
        const float ew[8] = {e0.x, e0.y, e0.z, e0.w, e1.x, e1.y, e1.z, e1.w};
        float4 o[4];
        #pragma unroll
        for (int j = 0; j < 4; ++j)
            o[j] = make_float4(sbo[j*4], sbo[j*4+1], sbo[j*4+2], sbo[j*4+3]);
        #pragma unroll
        for (int a = 0; a < NA; ++a) {
            const float w = ew[a];
            const float4* mrow = (const float4*)(sM + a * NOUT);
            #pragma unroll
            for (int j = 0; j < 4; ++j) {
                const float4 m = mrow[j];
                o[j].x += w * m.x; o[j].y += w * m.y;
                o[j].z += w * m.z; o[j].w += w * m.w;
            }
        }
        op[0] = o[0]; op[1] = o[1]; op[2] = o[2]; op[3] = o[3];
    } else {
        op[0] = z; op[1] = z; op[2] = z; op[3] = z;
    }
}

extern "C" void kernel_launch(void* const* d_in, const int* in_sizes, int n_in,
                              void* d_out, int out_size) {
    const float* data       = (const float*)d_in[0];
    const int*   num_vertex = (const int*)  d_in[1];
    const float* W_flr      = (const float*)d_in[2];
    const float* b_flr      = (const float*)d_in[3];
    const float* W_s        = (const float*)d_in[4];
    const float* b_s        = (const float*)d_in[5];
    const float* W_out      = (const float*)d_in[6];
    const float* b_out      = (const float*)d_in[7];
    float* out = (float*)d_out;

    garnet<<<GRID1, 256>>>(data, num_vertex, W_flr, b_flr,
                           W_s, b_s, W_out, b_out, out);
}